// round 4
// baseline (speedup 1.0000x reference)
#include <cuda_runtime.h>

#define NN 100000
#define NP 100032          // padded to 1563*64
#define EI 800000
#define EE 400000
#define HH 128
#define GG 256
#define N_LAYERS 4
#define NTILES 1563        // NP/64

// ---------------- scratch (static __device__, no runtime alloc) ----------------
__device__ float g_h [NP*HH];   // h buffer A
__device__ float g_hb[NP*HH];   // h buffer B (double-buffer across layers)
__device__ float g_vp[NP*HH];
__device__ float g_vl[NP*HH];
__device__ float g_wint[EE];
__device__ int   g_degi[NN];   // zeroed by k_fc tail each call (zero-init on load)
__device__ int   g_dege[NN];
__device__ float g_sif[NN];    // 1/(deg_i+1)
__device__ float g_bfi[NN];    // deg_i/(deg_i+1)
__device__ float g_sef[NN];    // log(deg_e+1)
__device__ float g_bfe[NN];    // deg_e*log(deg_e+1)
__device__ int   g_offi[NN+1];
__device__ int   g_offe[NN+1];
__device__ int   g_curi[NN];
__device__ int   g_cure[NN];
__device__ int   g_srci[EI];
__device__ float g_wi[EI];
__device__ int   g_srce[EE];
__device__ float g_we[EE];
__device__ int   g_parti[128];
__device__ int   g_parte[128];
__device__ float g_pool[GG*HH];

__device__ __forceinline__ float silu_f(float x){ return x / (1.f + __expf(-x)); }
__device__ __forceinline__ unsigned long long dup2(float a){
    unsigned long long r; asm("mov.b64 %0, {%1, %1};" : "=l"(r) : "f"(a)); return r;
}
__device__ __forceinline__ void ffma2(unsigned long long& acc, unsigned long long a, unsigned long long b){
    asm("fma.rn.f32x2 %0, %1, %2, %0;" : "+l"(acc) : "l"(a), "l"(b));
}

// ---------------- 1: degree counts + inter weight + pool zero ----------------
__global__ void k_count(const int* __restrict__ ei, const int* __restrict__ ee,
                        const float* __restrict__ pos){
    int t = blockIdx.x*blockDim.x + threadIdx.x;
    if (t < EI){
        atomicAdd(&g_degi[ei[EI+t]], 1);
    } else if (t < EI+EE){
        int e = t - EI;
        int s = ee[e], d = ee[EE+e];
        float dx = pos[s*3+0]-pos[d*3+0];
        float dy = pos[s*3+1]-pos[d*3+1];
        float dz = pos[s*3+2]-pos[d*3+2];
        g_wint[e] = __expf(-(dx*dx+dy*dy+dz*dz));
        atomicAdd(&g_dege[d], 1);
    } else if (t < EI+EE+GG*HH){
        g_pool[t - EI - EE] = 0.f;
    }
}

// ---------------- 2: per-chunk inclusive scan (1024 nodes/block) ----------------
__global__ void k_scan1(){
    __shared__ int s[1024];
    int b0 = blockIdx.x*1024;
    for (int pass = 0; pass < 2; pass++){
        const int* deg = pass ? g_dege : g_degi;
        int* off  = pass ? g_offe : g_offi;
        int* part = pass ? g_parte : g_parti;
        for (int i = threadIdx.x; i < 1024; i += 256){
            int n = b0 + i; s[i] = (n < NN) ? deg[n] : 0;
        }
        __syncthreads();
        for (int d = 1; d < 1024; d <<= 1){
            int t[4];
            #pragma unroll
            for (int j = 0; j < 4; j++){
                int i = threadIdx.x + j*256;
                t[j] = (i >= d) ? s[i-d] : 0;
            }
            __syncthreads();
            #pragma unroll
            for (int j = 0; j < 4; j++){
                int i = threadIdx.x + j*256;
                s[i] += t[j];
            }
            __syncthreads();
        }
        for (int i = threadIdx.x; i < 1024; i += 256){
            int n = b0 + i; if (n < NN) off[n+1] = s[i];
        }
        if (threadIdx.x == 0) part[blockIdx.x] = s[1023];
        __syncthreads();
    }
}

// ---------------- 3: add chunk bases + cursors + degree factors ----------------
__global__ void k_scan2(){
    __shared__ int spi[128], spe[128];
    int b = blockIdx.x, t = threadIdx.x;
    if (t < 128){
        spi[t] = (t < 98) ? g_parti[t] : 0;
        spe[t] = (t < 98) ? g_parte[t] : 0;
    }
    __syncthreads();
    for (int d = 1; d < 128; d <<= 1){
        int vi = 0, ve = 0;
        if (t < 128 && t >= d){ vi = spi[t-d]; ve = spe[t-d]; }
        __syncthreads();
        if (t < 128){ spi[t] += vi; spe[t] += ve; }
        __syncthreads();
    }
    int basei = (b > 0) ? spi[b-1] : 0;
    int basee = (b > 0) ? spe[b-1] : 0;
    int b0 = b*1024;
    for (int i = t; i < 1024; i += 256){
        int n = b0 + i;
        if (n >= NN) continue;
        int di = g_degi[n], de = g_dege[n];
        int oi = g_offi[n+1] + basei;
        int oe = g_offe[n+1] + basee;
        g_offi[n+1] = oi;
        g_offe[n+1] = oe;
        g_curi[n] = oi - di;
        g_cure[n] = oe - de;
        if (n == 0){ g_offi[0] = 0; g_offe[0] = 0; }
        float fdi = (float)di, fde = (float)de;
        float inv = 1.f/(fdi+1.f);
        g_sif[n] = inv;
        g_bfi[n] = fdi*inv;
        float L = logf(fde+1.f);
        g_sef[n] = L;
        g_bfe[n] = fde*L;
    }
}

// ---------------- 4: fill CSR (src + weight, grouped by dst) ----------------
__global__ void k_fill(const int* __restrict__ ei, const float* __restrict__ ea,
                       const int* __restrict__ ee){
    int t = blockIdx.x*blockDim.x + threadIdx.x;
    if (t < EI){
        int s = ei[t], d = ei[EI+t];
        int p = atomicAdd(&g_curi[d], 1);
        g_srci[p] = s; g_wi[p] = ea[t];
    } else if (t < EI+EE){
        int e = t - EI;
        int s = ee[e], d = ee[EE+e];
        int p = atomicAdd(&g_cure[d], 1);
        g_srce[p] = s; g_we[p] = g_wint[e];
    }
}

// ---------------- 5: node init (lin_node + SiLU) + zero vp/vl ----------------
__global__ void k_node_init(const float* __restrict__ x,
                            const float* __restrict__ W,
                            const float* __restrict__ b){
    __shared__ float Ws[35*HH];
    __shared__ float xs[16*35];
    int t = threadIdx.x;           // 128
    int n0 = blockIdx.x*16;
    for (int i = t; i < 35*HH; i += 128) Ws[i] = W[i];
    for (int i = t; i < 16*35; i += 128){
        int node = i/35, k = i - node*35;
        xs[i] = x[(n0+node)*35 + k];
    }
    __syncthreads();
    float bb = b[t];
    for (int node = 0; node < 16; node++){
        float acc = bb;
        #pragma unroll
        for (int k = 0; k < 35; k++) acc += xs[node*35+k]*Ws[k*HH+t];
        g_h[(n0+node)*HH + t] = silu_f(acc);
    }
    float4 z = make_float4(0.f,0.f,0.f,0.f);
    int base4 = n0*32;
    for (int i = t; i < 16*32; i += 128){
        ((float4*)g_vp)[base4+i] = z;
        ((float4*)g_vl)[base4+i] = z;
    }
}

// ---------------- fused per-layer: CSR gather -> dual GEMM -> SiLU update ----------------
// hin: read-only h for this layer (gather + residual). hout: updated h.
#define AST 132
#define SMEM_LAYER ((128*256 + 2*64*AST)*sizeof(float))   // 198656 B

__global__ void __launch_bounds__(256,1) k_layer(
        const float* __restrict__ hin, float* __restrict__ hout,
        const float* __restrict__ Wi, const float* __restrict__ We,
        const float* __restrict__ bi, const float* __restrict__ be)
{
    extern __shared__ float sm[];
    float* ws  = sm;                 // [128][256]: cols 0..127 Wi, 128..255 We
    float* asi = ws  + 128*256;      // [64][AST] A_i tile, reused as sv_p
    float* ase = asi + 64*AST;       // [64][AST] A_e tile, reused as sv_l
    int tid = threadIdx.x;
    int cg = tid & 31, rg = tid >> 5;
    int c4 = cg*4;

    for (int i = tid; i < 8192; i += 256){
        int k = i >> 6;
        int c = (i & 63)*4;
        float4 v = (c < 128) ? *(const float4*)&Wi[k*128 + c]
                             : *(const float4*)&We[k*128 + (c-128)];
        *(float4*)&ws[k*256 + c] = v;
    }
    float4 bvi = *(const float4*)&bi[c4];
    float4 bve = *(const float4*)&be[c4];

    for (int tile = blockIdx.x; tile < NTILES; tile += gridDim.x){
        int n0 = tile*64;

        // ---- Phase A: gather CSR directly into smem A tiles (reads hin only) ----
        #pragma unroll 1
        for (int r = 0; r < 8; r++){
            int nl = rg*8 + r;
            int n  = n0 + nl;
            float4 ai = make_float4(0.f,0.f,0.f,0.f);
            float4 ae = make_float4(0.f,0.f,0.f,0.f);
            if (n < NN){
                // intra
                {
                    int a0 = g_offi[n], a1 = g_offi[n+1];
                    float4 x0 = make_float4(0,0,0,0), x1 = x0, x2 = x0, x3 = x0;
                    int j = a0;
                    for (; j + 4 <= a1; j += 4){
                        int s0 = __ldg(&g_srci[j+0]); float w0 = __ldg(&g_wi[j+0]);
                        int s1 = __ldg(&g_srci[j+1]); float w1 = __ldg(&g_wi[j+1]);
                        int s2 = __ldg(&g_srci[j+2]); float w2 = __ldg(&g_wi[j+2]);
                        int s3 = __ldg(&g_srci[j+3]); float w3 = __ldg(&g_wi[j+3]);
                        float4 h0 = *(const float4*)&hin[s0*HH + c4];
                        float4 h1 = *(const float4*)&hin[s1*HH + c4];
                        float4 h2 = *(const float4*)&hin[s2*HH + c4];
                        float4 h3 = *(const float4*)&hin[s3*HH + c4];
                        x0.x += w0*h0.x; x0.y += w0*h0.y; x0.z += w0*h0.z; x0.w += w0*h0.w;
                        x1.x += w1*h1.x; x1.y += w1*h1.y; x1.z += w1*h1.z; x1.w += w1*h1.w;
                        x2.x += w2*h2.x; x2.y += w2*h2.y; x2.z += w2*h2.z; x2.w += w2*h2.w;
                        x3.x += w3*h3.x; x3.y += w3*h3.y; x3.z += w3*h3.z; x3.w += w3*h3.w;
                    }
                    for (; j < a1; j++){
                        int s = __ldg(&g_srci[j]); float w = __ldg(&g_wi[j]);
                        float4 hv = *(const float4*)&hin[s*HH + c4];
                        x0.x += w*hv.x; x0.y += w*hv.y; x0.z += w*hv.z; x0.w += w*hv.w;
                    }
                    float sc = g_sif[n];
                    ai.x = (x0.x+x1.x+x2.x+x3.x)*sc;
                    ai.y = (x0.y+x1.y+x2.y+x3.y)*sc;
                    ai.z = (x0.z+x1.z+x2.z+x3.z)*sc;
                    ai.w = (x0.w+x1.w+x2.w+x3.w)*sc;
                }
                // inter
                {
                    int a0 = g_offe[n], a1 = g_offe[n+1];
                    float4 x0 = make_float4(0,0,0,0), x1 = x0, x2 = x0, x3 = x0;
                    int j = a0;
                    for (; j + 4 <= a1; j += 4){
                        int s0 = __ldg(&g_srce[j+0]); float w0 = __ldg(&g_we[j+0]);
                        int s1 = __ldg(&g_srce[j+1]); float w1 = __ldg(&g_we[j+1]);
                        int s2 = __ldg(&g_srce[j+2]); float w2 = __ldg(&g_we[j+2]);
                        int s3 = __ldg(&g_srce[j+3]); float w3 = __ldg(&g_we[j+3]);
                        float4 h0 = *(const float4*)&hin[s0*HH + c4];
                        float4 h1 = *(const float4*)&hin[s1*HH + c4];
                        float4 h2 = *(const float4*)&hin[s2*HH + c4];
                        float4 h3 = *(const float4*)&hin[s3*HH + c4];
                        x0.x += w0*h0.x; x0.y += w0*h0.y; x0.z += w0*h0.z; x0.w += w0*h0.w;
                        x1.x += w1*h1.x; x1.y += w1*h1.y; x1.z += w1*h1.z; x1.w += w1*h1.w;
                        x2.x += w2*h2.x; x2.y += w2*h2.y; x2.z += w2*h2.z; x2.w += w2*h2.w;
                        x3.x += w3*h3.x; x3.y += w3*h3.y; x3.z += w3*h3.z; x3.w += w3*h3.w;
                    }
                    for (; j < a1; j++){
                        int s = __ldg(&g_srce[j]); float w = __ldg(&g_we[j]);
                        float4 hv = *(const float4*)&hin[s*HH + c4];
                        x0.x += w*hv.x; x0.y += w*hv.y; x0.z += w*hv.z; x0.w += w*hv.w;
                    }
                    float sc = g_sef[n];
                    ae.x = (x0.x+x1.x+x2.x+x3.x)*sc;
                    ae.y = (x0.y+x1.y+x2.y+x3.y)*sc;
                    ae.z = (x0.z+x1.z+x2.z+x3.z)*sc;
                    ae.w = (x0.w+x1.w+x2.w+x3.w)*sc;
                }
            }
            *(float4*)&asi[nl*AST + c4] = ai;
            *(float4*)&ase[nl*AST + c4] = ae;
        }
        __syncthreads();

        // ---- Phase B: dual GEMM (FFMA2) ----
        unsigned long long acci[8][2], acce[8][2];
        #pragma unroll
        for (int r = 0; r < 8; r++){ acci[r][0]=0ull; acci[r][1]=0ull; acce[r][0]=0ull; acce[r][1]=0ull; }

        const float* arow_i = asi + rg*8*AST;
        const float* arow_e = ase + rg*8*AST;

        #pragma unroll 2
        for (int k0 = 0; k0 < 128; k0 += 4){
            float4 a4[8];
            #pragma unroll
            for (int r = 0; r < 8; r++) a4[r] = *(const float4*)&arow_i[r*AST + k0];
            #pragma unroll
            for (int kk = 0; kk < 4; kk++){
                ulonglong2 w2 = *(const ulonglong2*)&ws[(k0+kk)*256 + c4];
                #pragma unroll
                for (int r = 0; r < 8; r++){
                    float a = (kk==0)?a4[r].x:(kk==1)?a4[r].y:(kk==2)?a4[r].z:a4[r].w;
                    unsigned long long aa = dup2(a);
                    ffma2(acci[r][0], aa, w2.x);
                    ffma2(acci[r][1], aa, w2.y);
                }
            }
        }
        #pragma unroll 2
        for (int k0 = 0; k0 < 128; k0 += 4){
            float4 a4[8];
            #pragma unroll
            for (int r = 0; r < 8; r++) a4[r] = *(const float4*)&arow_e[r*AST + k0];
            #pragma unroll
            for (int kk = 0; kk < 4; kk++){
                ulonglong2 w2 = *(const ulonglong2*)&ws[(k0+kk)*256 + 128 + c4];
                #pragma unroll
                for (int r = 0; r < 8; r++){
                    float a = (kk==0)?a4[r].x:(kk==1)?a4[r].y:(kk==2)?a4[r].z:a4[r].w;
                    unsigned long long aa = dup2(a);
                    ffma2(acce[r][0], aa, w2.x);
                    ffma2(acce[r][1], aa, w2.y);
                }
            }
        }

        // ---- Phase C: epilogue (bias + old state + SiLU), stage into smem ----
        #pragma unroll
        for (int r = 0; r < 8; r++){
            int nl = rg*8 + r;
            int n  = n0 + nl;
            if (n >= NN) continue;
            float bf   = g_bfi[n];
            float bfe_ = g_bfe[n];
            float2 p0 = *(float2*)&acci[r][0];
            float2 p1 = *(float2*)&acci[r][1];
            float4 vo = *(const float4*)&g_vp[n*HH + c4];
            float4 v;
            v.x = silu_f(p0.x + bvi.x*bf + vo.x);
            v.y = silu_f(p0.y + bvi.y*bf + vo.y);
            v.z = silu_f(p1.x + bvi.z*bf + vo.z);
            v.w = silu_f(p1.y + bvi.w*bf + vo.w);
            *(float4*)&g_vp[n*HH + c4] = v;
            *(float4*)&asi[nl*AST + c4] = v;

            float2 q0 = *(float2*)&acce[r][0];
            float2 q1 = *(float2*)&acce[r][1];
            float4 uo = *(const float4*)&g_vl[n*HH + c4];
            float4 u;
            u.x = silu_f(q0.x + bve.x*bfe_ + uo.x);
            u.y = silu_f(q0.y + bve.y*bfe_ + uo.y);
            u.z = silu_f(q1.x + bve.z*bfe_ + uo.z);
            u.w = silu_f(q1.y + bve.w*bfe_ + uo.w);
            *(float4*)&g_vl[n*HH + c4] = u;
            *(float4*)&ase[nl*AST + c4] = u;
        }
        __syncthreads();

        // ---- Phase D: hout = hin + v_p + v_l ----
        for (int i = tid; i < 2048; i += 256){
            int row = i >> 5, kc = (i & 31)*4;
            int n = n0 + row;
            if (n >= NN) continue;
            int goff = n*HH + kc;
            float4 hv = *(const float4*)&hin[goff];
            float4 p  = *(const float4*)&asi[row*AST + kc];
            float4 q  = *(const float4*)&ase[row*AST + kc];
            hv.x += p.x+q.x; hv.y += p.y+q.y; hv.z += p.z+q.z; hv.w += p.w+q.w;
            *(float4*)&hout[goff] = hv;
        }
        __syncthreads();
    }
}

// ---------------- pooling ----------------
__global__ void k_pool(const int* __restrict__ batch){
    __shared__ int sb[512];
    int c = threadIdx.x;              // 128 cols
    int n0 = blockIdx.x*512;
    if (n0 >= NN) return;
    int nend = min(n0+512, NN);
    int cnt = nend - n0;
    for (int i = c; i < cnt; i += 128) sb[i] = batch[n0+i];
    __syncthreads();
    int cur = sb[0];
    float acc = 0.f;
    for (int k = 0; k < cnt; k++){
        int b = sb[k];
        if (b != cur){
            atomicAdd(&g_pool[cur*HH+c], acc);
            acc = 0.f; cur = b;
        }
        acc += g_h[(n0+k)*HH+c];
    }
    atomicAdd(&g_pool[cur*HH+c], acc);
}

// ---------------- FC head (+ degree re-zero for next graph replay) ----------------
__global__ void k_fc(const float* __restrict__ fcW, const float* __restrict__ fcb,
                     const float* __restrict__ gam, const float* __restrict__ bet,
                     const float* __restrict__ oW,  const float* __restrict__ ob,
                     float* __restrict__ out){
    int g = blockIdx.x, c = threadIdx.x;  // 128 threads
    __shared__ float s[HH];
    __shared__ float red[HH];
    s[c] = g_pool[g*HH + c];
    // re-zero degree counters so the next kernel_launch call starts clean
    for (int i = g*128 + c; i < NN; i += GG*128){ g_degi[i] = 0; g_dege[i] = 0; }
    __syncthreads();
    const float bns = rsqrtf(1.f + 1e-5f);
    for (int j = 0; j < 3; j++){
        const float* W = fcW + j*HH*HH;
        float acc = fcb[j*HH+c];
        #pragma unroll 8
        for (int k = 0; k < HH; k++) acc += s[k]*W[k*HH+c];
        acc = acc > 0.f ? acc : 0.01f*acc;
        acc = acc*bns*gam[j*HH+c] + bet[j*HH+c];
        __syncthreads();
        s[c] = acc;
        __syncthreads();
    }
    red[c] = s[c]*oW[c];
    __syncthreads();
    for (int o = 64; o > 0; o >>= 1){
        if (c < o) red[c] += red[c+o];
        __syncthreads();
    }
    if (c == 0) out[g] = red[0] + ob[0];
}

// ---------------- host ----------------
extern "C" void kernel_launch(void* const* d_in, const int* in_sizes, int n_in,
                              void* d_out, int out_size){
    const float* x    = (const float*)d_in[0];
    const int*   ei   = (const int*)  d_in[1];
    const int*   ee   = (const int*)  d_in[2];
    const float* pos  = (const float*)d_in[3];
    const float* ea   = (const float*)d_in[4];
    const int*   batch= (const int*)  d_in[5];
    const float* lnW  = (const float*)d_in[6];
    const float* lnb  = (const float*)d_in[7];
    const float* Wi   = (const float*)d_in[8];
    const float* bi   = (const float*)d_in[9];
    const float* We   = (const float*)d_in[10];
    const float* be   = (const float*)d_in[11];
    const float* fcW  = (const float*)d_in[12];
    const float* fcb  = (const float*)d_in[13];
    const float* gam  = (const float*)d_in[14];
    const float* bet  = (const float*)d_in[15];
    const float* oW   = (const float*)d_in[16];
    const float* ob   = (const float*)d_in[17];
    float* out = (float*)d_out;

    cudaFuncSetAttribute(k_layer, cudaFuncAttributeMaxDynamicSharedMemorySize, (int)SMEM_LAYER);

    // device pointers to the two h buffers
    float *hA, *hB;
    cudaGetSymbolAddress((void**)&hA, g_h);
    cudaGetSymbolAddress((void**)&hB, g_hb);

    k_count<<<(EI+EE+GG*HH+255)/256, 256>>>(ei, ee, pos);     // 1
    k_scan1<<<98, 256>>>();                                   // 2
    k_scan2<<<98, 256>>>();                                   // 3
    k_fill<<<(EI+EE+255)/256, 256>>>(ei, ea, ee);             // 4 (ncu capture slot)
    k_node_init<<<NN/16, 128>>>(x, lnW, lnb);                 // 5

    for (int l = 0; l < N_LAYERS; l++){
        const float* hin  = (l & 1) ? hB : hA;
        float*       hout = (l & 1) ? hA : hB;
        k_layer<<<148, 256, SMEM_LAYER>>>(hin, hout,
                                          Wi + l*HH*HH, We + l*HH*HH,
                                          bi + l*HH,    be + l*HH);   // 6-9
    }
    // after 4 layers (even count), final h is back in g_h (hA)

    k_pool<<<(NN+511)/512, 128>>>(batch);                     // 10
    k_fc<<<GG, 128>>>(fcW, fcb, gam, bet, oW, ob, out);       // 11
}